// round 16
// baseline (speedup 1.0000x reference)
#include <cuda_runtime.h>
#include <cuda_fp16.h>
#include <math.h>
#include <stdint.h>

#define NPTS 2048
#define NB   8
#define BN   (NPTS*NB)
#define DD   16
#define KSEL 32
#define CAND_MAX 96
#define WPB  4

#define GX 20
#define GY 20
#define NCELL (GX*GY)
#define ORG  (-0.80f)
#define CINV (12.5f)   // 1/0.08

static __device__ __align__(16) uint32_t g_Ah[BN*32];      // f16x2 A rows, kt-pair-permuted
static __device__ __align__(16) uint32_t g_Bh[BN*32];      // f16x2 B rows, kt-pair-permuted
static __device__ __align__(16) float2   g_pos[BN];
static __device__ __align__(16) float    g_grad[BN*DD];
static __device__ __align__(16) float    g_xbuf[BN*DD];
static __device__ __align__(16) float    g_UVt[64*32];
static __device__ __align__(16) uint32_t g_UVf2[4*4*64];   // f16x2 B-frags [(kt*4+nt)][lane][2]
static __device__ __align__(16) float    g_su[32];
static __device__ int    g_cnt[NB*NCELL];
static __device__ int    g_start[NB*(NCELL+1)];
static __device__ __align__(16) float4 g_spt[BN];

__device__ __forceinline__ uint32_t pkh2(float hi, float lo) {
    uint32_t r; asm("cvt.rn.f16x2.f32 %0, %1, %2;" : "=r"(r) : "f"(hi), "f"(lo)); return r;
}
__device__ __forceinline__ uint32_t hadd2(uint32_t a, uint32_t b) {
    uint32_t r; asm("add.rn.f16x2 %0, %1, %2;" : "=r"(r) : "r"(a), "r"(b)); return r;
}
__device__ __forceinline__ uint32_t hmul2(uint32_t a, uint32_t b) {
    uint32_t r; asm("mul.rn.f16x2 %0, %1, %2;" : "=r"(r) : "r"(a), "r"(b)); return r;
}
__device__ __forceinline__ uint32_t tanh2(uint32_t a) {
    uint32_t r; asm("tanh.approx.f16x2 %0, %1;" : "=r"(r) : "r"(a)); return r;
}
__device__ __forceinline__ void red_add_v2(float* p, float a, float b) {
    asm volatile("red.global.add.v2.f32 [%0], {%1,%2};" :: "l"(p), "f"(a), "f"(b) : "memory");
}
__device__ __forceinline__ void red_add_v4(float* p, float a, float b, float c, float d) {
    asm volatile("red.global.add.v4.f32 [%0], {%1,%2,%3,%4};"
                 :: "l"(p), "f"(a), "f"(b), "f"(c), "f"(d) : "memory");
}
__device__ __forceinline__ void mma_f16(float* c, const uint32_t* a, uint32_t b0, uint32_t b1) {
    asm("mma.sync.aligned.m16n8k16.row.col.f32.f16.f16.f32 "
        "{%0,%1,%2,%3}, {%4,%5,%6,%7}, {%8,%9}, {%0,%1,%2,%3};"
        : "+f"(c[0]), "+f"(c[1]), "+f"(c[2]), "+f"(c[3])
        : "r"(a[0]), "r"(a[1]), "r"(a[2]), "r"(a[3]), "r"(b0), "r"(b1));
}
__device__ __forceinline__ int cell1d(float v) {
    int c = (int)floorf((v - ORG) * CINV);
    return min(max(c, 0), GX - 1);
}
__device__ __forceinline__ int permw(int l) {
    return 8*(l >> 3) + 2*(l & 3) + ((l >> 2) & 1);
}

__global__ void prep_kernel(const float* __restrict__ W1,
                            const float* __restrict__ W2,
                            const float* __restrict__ Wout) {
    int h = threadIdx.x;  // 64
    for (int t = h; t < NB*NCELL; t += 64) g_cnt[t] = 0;
    float wv = 0.f;
    #pragma unroll
    for (int c = 0; c < 32; c++) wv = fmaf(W2[h*32 + c], Wout[c], wv);
    #pragma unroll
    for (int d = 0; d < 16; d++) {
        g_UVt[h*32 + d]      = W1[d*64 + h]      * wv;
        g_UVt[h*32 + 16 + d] = W1[(16+d)*64 + h] * wv;
    }
    __syncthreads();
    if (h < 32) {
        float s = 0.f;
        for (int hh = 0; hh < 64; hh++) s += g_UVt[hh*32 + h];
        g_su[h] = s;
        int g = h >> 2, tg = h & 3;
        for (int kt = 0; kt < 4; kt++)
            for (int nt = 0; nt < 4; nt++) {
                int col = nt*8 + g;
                float u0 = g_UVt[(kt*16 + 2*tg    )*32 + col];
                float u1 = g_UVt[(kt*16 + 2*tg + 1)*32 + col];
                float u2 = g_UVt[(kt*16 + 8 + 2*tg    )*32 + col];
                float u3 = g_UVt[(kt*16 + 8 + 2*tg + 1)*32 + col];
                g_UVf2[((kt*4 + nt)*32 + h)*2 + 0] = pkh2(u1, u0);
                g_UVf2[((kt*4 + nt)*32 + h)*2 + 1] = pkh2(u3, u2);
            }
    }
}

__global__ void __launch_bounds__(512) binps_kernel() {
    __shared__ int wsum[16];
    __shared__ int s_cur[NCELL];
    int b = blockIdx.x;
    int c = threadIdx.x;
    int lane = c & 31, wid = c >> 5;
    int v = (c < NCELL) ? g_cnt[b*NCELL + c] : 0;
    int sv = v;
    #pragma unroll
    for (int o = 1; o < 32; o <<= 1) {
        int t = __shfl_up_sync(0xffffffffu, sv, o);
        if (lane >= o) sv += t;
    }
    if (lane == 31) wsum[wid] = sv;
    __syncthreads();
    if (wid == 0) {
        int t = (lane < 16) ? wsum[lane] : 0;
        #pragma unroll
        for (int o = 1; o < 16; o <<= 1) {
            int u = __shfl_up_sync(0xffffffffu, t, o);
            if (lane >= o) t += u;
        }
        if (lane < 16) wsum[lane] = t;
    }
    __syncthreads();
    int incl = sv + (wid > 0 ? wsum[wid - 1] : 0);
    if (c < NCELL) {
        int ex = incl - v;
        g_start[b*(NCELL+1) + c] = ex;
        s_cur[c] = ex;
        g_cnt[b*NCELL + c] = 0;
        if (c == NCELL - 1) g_start[b*(NCELL+1) + NCELL] = incl;
    }
    __syncthreads();
    #pragma unroll
    for (int k = 0; k < NPTS/512; k++) {
        int il = k*512 + c;
        float2 pos = g_pos[b*NPTS + il];
        int cell = cell1d(pos.y) * GX + cell1d(pos.x);
        int slot = atomicAdd(&s_cur[cell], 1);
        g_spt[b*NPTS + slot] = make_float4(pos.x, pos.y, __int_as_float(il), 0.f);
    }
}

__global__ void __launch_bounds__(512) updfeat_kernel(const float* __restrict__ xin,
                                                      const float* __restrict__ W1,
                                                      const float* __restrict__ b1,
                                                      float* __restrict__ out,
                                                      float scale, int use_buf) {
    __shared__ __align__(16) float sW[2048];
    __shared__ float sb[64];
    int tid  = threadIdx.x;
    int lane = tid & 31;
    int wid  = tid >> 5;
    for (int t = tid; t < 2048; t += 512) sW[t] = W1[t];
    if (tid < 64) sb[tid] = b1[tid];
    __syncthreads();

    int pw = permw(lane);
    const float* xs = use_buf ? g_xbuf : xin;
    #pragma unroll
    for (int it = 0; it < 4; it++) {
        int p = blockIdx.x * 64 + wid * 4 + it;
        float xval = 0.f;
        if (lane < 16) {
            float v = xs[p*DD + lane] - scale * g_grad[p*DD + lane];
            xval = v;
            g_xbuf[p*DD + lane] = v;
            out[p*DD + lane]    = v;
            g_grad[p*DD + lane] = 0.f;
        }
        float a0 = sb[2*lane], a1 = sb[2*lane + 1];
        float c0 = 0.f, c1 = 0.f;
        #pragma unroll
        for (int d = 0; d < 16; d++) {
            float xd = __shfl_sync(0xffffffffu, xval, d);
            float2 wa = *reinterpret_cast<const float2*>(&sW[d*64 + 2*lane]);
            float2 wb = *reinterpret_cast<const float2*>(&sW[(16 + d)*64 + 2*lane]);
            a0 = fmaf(xd, wa.x, a0);
            a1 = fmaf(xd, wa.y, a1);
            c0 = fmaf(xd, wb.x, c0);
            c1 = fmaf(xd, wb.y, c1);
        }
        g_Ah[(size_t)p*32 + pw] = pkh2(a1, a0);
        g_Bh[(size_t)p*32 + pw] = pkh2(c1, c0);
        float v0 = __shfl_sync(0xffffffffu, xval, 0);
        float v1 = __shfl_sync(0xffffffffu, xval, 1);
        if (lane == 0) {
            g_pos[p] = make_float2(v0, v1);
            int b = p / NPTS;
            int cell = cell1d(v1) * GX + cell1d(v0);
            atomicAdd(&g_cnt[b*NCELL + cell], 1);
        }
    }
}

__global__ void __launch_bounds__(512) finupd_kernel(float* __restrict__ out) {
    int i = blockIdx.x * 512 + threadIdx.x;
    out[i] = g_xbuf[i] - 0.01f * g_grad[i];
}

__global__ void __launch_bounds__(128, 11) edges_kernel() {
    // all SMEM per-warp; s_key ALIASES s_Bf (keys dead before staging writes)
    __shared__ __align__(16) uint32_t s_Bf[WPB*1024];   // 16 KB
    __shared__ __align__(8)  uint32_t s_Ai2[WPB][32];   // 512 B
    __shared__ int      s_sel[WPB][KSEL];               // 512 B

    const float R2 = 0.08f * 0.08f;
    int tid  = threadIdx.x;
    int lane = tid & 31;
    int w    = tid >> 5;
    int batch = blockIdx.x >> 9;
    int grp   = blockIdx.x & 511;
    int base  = batch * NPTS;

    int il = grp * WPB + w;
    int ig = base + il;
    float2 pi = __ldg(&g_pos[ig]);

    uint32_t* Bfw = s_Bf + w*1024;
    uint64_t* keyw = reinterpret_cast<uint64_t*>(Bfw);   // alias: first 768B of warp's Bf region

    s_Ai2[w][lane] = __ldg(&g_Ah[(size_t)ig*32 + lane]);
    s_sel[w][lane] = il;
    __syncwarp();

    // ---- binned candidate scan ----
    int cx = cell1d(pi.x), cy = cell1d(pi.y);
    int ry0 = max(cy - 1, 0), ry1 = min(cy + 1, GY - 1);
    int rx0 = max(cx - 1, 0), rx1 = min(cx + 1, GX - 1);
    const int* startb = g_start + batch*(NCELL+1);
    int cnt = 0;
    unsigned lt = (1u << lane) - 1u;
    for (int ry = ry0; ry <= ry1; ry++) {
        int s = __ldg(startb + ry*GX + rx0);
        int e = __ldg(startb + ry*GX + rx1 + 1);
        for (int tb = s; tb < e; tb += 32) {
            int t = tb + lane;
            bool in = (t < e);
            float4 pj = in ? __ldg(&g_spt[base + t]) : make_float4(1e9f, 1e9f, 0.f, 0.f);
            int jl = __float_as_int(pj.z);
            float dx = pj.x - pi.x, dy = pj.y - pi.y;
            float d2 = fmaf(dx, dx, dy*dy);
            bool ok = in && (d2 < R2) && (jl != il);
            unsigned m = __ballot_sync(0xffffffffu, ok);
            if (ok) {
                int p = cnt + __popc(m & lt);
                if (p < CAND_MAX)
                    keyw[p] = (((uint64_t)__float_as_uint(d2)) << 32) | (uint32_t)jl;
            }
            cnt += __popc(m);
        }
    }
    int M = min(cnt, CAND_MAX);
    __syncwarp();

    // ---- select K smallest: single-pass multi-rank loop ----
    int S;
    if (M <= KSEL) {
        if (lane < M) s_sel[w][lane] = (int)(uint32_t)keyw[lane];
        S = M;
    } else {
        if (lane == 0 && M < CAND_MAX) keyw[M] = ~0ull;
        __syncwarp();
        uint64_t k0 = keyw[lane];
        uint64_t k1 = (lane + 32 < M) ? keyw[lane + 32] : ~0ull;
        uint64_t k2 = (lane + 64 < M) ? keyw[lane + 64] : ~0ull;
        int r0 = 0, r1 = 0, r2 = 0;
        int Mr = (M + 1) & ~1;
        #pragma unroll 2
        for (int t = 0; t < Mr; t += 2) {
            uint64_t ta = keyw[t];
            uint64_t tb = keyw[t + 1];
            r0 += (int)(ta < k0) + (int)(tb < k0);
            r1 += (int)(ta < k1) + (int)(tb < k1);
            r2 += (int)(ta < k2) + (int)(tb < k2);
        }
        if (r0 < KSEL) s_sel[w][r0] = (int)(uint32_t)k0;
        if (lane + 32 < M && r1 < KSEL) s_sel[w][r1] = (int)(uint32_t)k1;
        if (lane + 64 < M && r2 < KSEL) s_sel[w][r2] = (int)(uint32_t)k2;
        S = KSEL;
    }
    __syncwarp();   // keys fully consumed; Bfw may now be overwritten

    // ---- stage B rows, swizzle: word W of row r -> r*32+((W+4r)&31) ----
    int sel_own = s_sel[w][lane];
    int q = lane & 7;
    #pragma unroll
    for (int i = 0; i < 8; i++) {
        int r  = 4*i + (lane >> 3);
        int jl = __shfl_sync(0xffffffffu, sel_own, r);
        uint4 v = __ldg(reinterpret_cast<const uint4*>(g_Bh + (size_t)(base + jl)*32) + q);
        int word = r*32 + ((4*q + 4*r) & 31);
        *reinterpret_cast<uint4*>(Bfw + word) = v;
    }
    __syncwarp();

    // ---- per-warp GEMM via f16 m16n8k16 ----
    int g2 = lane >> 2, tg = lane & 3;
    bool v0 = (g2      < S), v1 = (g2 + 8  < S);
    bool v2f = (g2 + 16 < S), v3 = (g2 + 24 < S);
    float acci[2][4];
    float accj[2][2][4];
    #pragma unroll
    for (int nt = 0; nt < 2; nt++)
        #pragma unroll
        for (int qq = 0; qq < 4; qq++) acci[nt][qq] = 0.f;
    #pragma unroll
    for (int mt = 0; mt < 2; mt++)
        #pragma unroll
        for (int nt = 0; nt < 2; nt++)
            #pragma unroll
            for (int qq = 0; qq < 4; qq++) accj[mt][nt][qq] = 0.f;

    const uint2* UV = reinterpret_cast<const uint2*>(g_UVf2);
    #pragma unroll
    for (int kt = 0; kt < 4; kt++) {
        uint2 ai = *reinterpret_cast<const uint2*>(&s_Ai2[w][kt*8 + 2*tg]);
        // single swizzle offset for all 4 fragment loads this kt:
        // 4*rB = 4*rA+32 == 4*rA (mod 32), 64*mt == 0 (mod 32)
        int off = (kt*8 + 2*tg + 4*g2) & 31;
        uint32_t A0[2][4];
        #pragma unroll
        for (int mt = 0; mt < 2; mt++) {
            int rA = mt*16 + g2, rB = rA + 8;
            uint2 bA = *reinterpret_cast<const uint2*>(Bfw + rA*32 + off);
            uint2 bB = *reinterpret_cast<const uint2*>(Bfw + rB*32 + off);
            uint32_t t0 = tanh2(hadd2(ai.x, bA.x));
            uint32_t t1 = tanh2(hadd2(ai.x, bB.x));
            uint32_t t2 = tanh2(hadd2(ai.y, bA.y));
            uint32_t t3 = tanh2(hadd2(ai.y, bB.y));
            bool vA = mt ? v2f : v0;
            bool vB = mt ? v3  : v1;
            A0[mt][0] = vA ? hmul2(t0, t0) : 0u;
            A0[mt][1] = vB ? hmul2(t1, t1) : 0u;
            A0[mt][2] = vA ? hmul2(t2, t2) : 0u;
            A0[mt][3] = vB ? hmul2(t3, t3) : 0u;
        }
        #pragma unroll
        for (int nt = 0; nt < 2; nt++) {
            uint2 bb = __ldg(UV + (kt*4 + nt)*32 + lane);
            mma_f16(acci[nt], A0[0], bb.x, bb.y);
            mma_f16(acci[nt], A0[1], bb.x, bb.y);
        }
        #pragma unroll
        for (int nt = 0; nt < 2; nt++) {
            uint2 bb = __ldg(UV + (kt*4 + nt + 2)*32 + lane);
            mma_f16(accj[0][nt], A0[0], bb.x, bb.y);
            mma_f16(accj[1][nt], A0[1], bb.x, bb.y);
        }
    }

    // ---- gj scatter ----
    float2 suv2 = __ldg(reinterpret_cast<const float2*>(g_su + 16 + 2*tg));
    float2 suv3 = __ldg(reinterpret_cast<const float2*>(g_su + 24 + 2*tg));
    float su16 = suv2.x, su17 = suv2.y;
    float su24 = suv3.x, su25 = suv3.y;
    bool evenTg = ((tg & 1) == 0);
    int colbase = (evenTg ? 0 : 8) + 4*(tg >> 1);
    #pragma unroll
    for (int mt = 0; mt < 2; mt++) {
        #pragma unroll
        for (int half = 0; half < 2; half++) {
            int h2 = half*2;
            float a0 = su16 - accj[mt][0][h2];
            float a1 = su17 - accj[mt][0][h2+1];
            float b0 = su24 - accj[mt][1][h2];
            float b1 = su25 - accj[mt][1][h2+1];
            float ra0 = __shfl_xor_sync(0xffffffffu, a0, 1);
            float ra1 = __shfl_xor_sync(0xffffffffu, a1, 1);
            float rb0 = __shfl_xor_sync(0xffffffffu, b0, 1);
            float rb1 = __shfl_xor_sync(0xffffffffu, b1, 1);
            float q0 = evenTg ? a0  : rb0;
            float q1 = evenTg ? a1  : rb1;
            float q2 = evenTg ? ra0 : b0;
            float q3 = evenTg ? ra1 : b1;
            int e = mt*16 + g2 + half*8;
            if (e < S) {
                int jg = base + s_sel[w][e];
                red_add_v4(g_grad + (size_t)jg*16 + colbase, q0, q1, q2, q3);
            }
        }
    }

    // ---- gi: column sums of cols 0..15 ----
    float s00 = acci[0][0] + acci[0][2];
    float s01 = acci[0][1] + acci[0][3];
    float s10 = acci[1][0] + acci[1][2];
    float s11 = acci[1][1] + acci[1][3];
    #pragma unroll
    for (int o = 4; o < 32; o <<= 1) {
        s00 += __shfl_xor_sync(0xffffffffu, s00, o);
        s01 += __shfl_xor_sync(0xffffffffu, s01, o);
        s10 += __shfl_xor_sync(0xffffffffu, s10, o);
        s11 += __shfl_xor_sync(0xffffffffu, s11, o);
    }
    if (g2 == 0) {
        float fs = (float)S;
        float2 su0 = __ldg(reinterpret_cast<const float2*>(g_su + 2*tg));
        float2 su1 = __ldg(reinterpret_cast<const float2*>(g_su + 8 + 2*tg));
        float* gp = g_grad + (size_t)ig*16;
        red_add_v2(gp + 2*tg,     fs*su0.x - s00, fs*su0.y - s01);
        red_add_v2(gp + 8 + 2*tg, fs*su1.x - s10, fs*su1.y - s11);
    }
}

extern "C" void kernel_launch(void* const* d_in, const int* in_sizes, int n_in,
                              void* d_out, int out_size) {
    (void)in_sizes; (void)n_in; (void)out_size;
    const float* x    = (const float*)d_in[0];
    const float* W1   = (const float*)d_in[1];
    const float* b1   = (const float*)d_in[2];
    const float* W2   = (const float*)d_in[3];
    const float* Wout = (const float*)d_in[5];
    float* out = (float*)d_out;

    prep_kernel<<<1, 64>>>(W1, W2, Wout);
    updfeat_kernel<<<BN/64, 512>>>(x, W1, b1, out, 0.0f, 0);
    binps_kernel<<<NB, 512>>>();
    edges_kernel<<<BN/WPB, 128>>>();                            // launch 4: profiled
    updfeat_kernel<<<BN/64, 512>>>(x, W1, b1, out, 0.01f, 1);
    binps_kernel<<<NB, 512>>>();
    edges_kernel<<<BN/WPB, 128>>>();
    finupd_kernel<<<(BN*DD)/512, 512>>>(out);
}

// round 17
// speedup vs baseline: 1.1176x; 1.1176x over previous
#include <cuda_runtime.h>
#include <cuda_fp16.h>
#include <math.h>
#include <stdint.h>

#define NPTS 2048
#define NB   8
#define BN   (NPTS*NB)
#define DD   16
#define KSEL 32
#define CAND_MAX 96
#define WPB  4

#define GX 20
#define GY 20
#define NCELL (GX*GY)
#define ORG  (-0.80f)
#define CINV (12.5f)   // 1/0.08

static __device__ __align__(16) uint32_t g_Ah[BN*32];      // f16x2 A rows, kt-pair-permuted
static __device__ __align__(16) uint32_t g_Bh[BN*32];      // f16x2 B rows, kt-pair-permuted
static __device__ __align__(16) float2   g_pos[BN];
static __device__ __align__(16) float    g_grad[BN*DD];
static __device__ __align__(16) float    g_xbuf[BN*DD];
static __device__ __align__(16) float    g_UVt[64*32];
static __device__ __align__(16) uint32_t g_UVf2[4*4*64];   // f16x2 B-frags [(kt*4+nt)][lane][2]
static __device__ __align__(16) float    g_su[32];
static __device__ int    g_cnt[NB*NCELL];
static __device__ int    g_start[NB*(NCELL+1)];
static __device__ __align__(16) float4 g_spt[BN];

__device__ __forceinline__ uint32_t pkh2(float hi, float lo) {
    uint32_t r; asm("cvt.rn.f16x2.f32 %0, %1, %2;" : "=r"(r) : "f"(hi), "f"(lo)); return r;
}
__device__ __forceinline__ uint32_t hadd2(uint32_t a, uint32_t b) {
    uint32_t r; asm("add.rn.f16x2 %0, %1, %2;" : "=r"(r) : "r"(a), "r"(b)); return r;
}
__device__ __forceinline__ uint32_t hmul2(uint32_t a, uint32_t b) {
    uint32_t r; asm("mul.rn.f16x2 %0, %1, %2;" : "=r"(r) : "r"(a), "r"(b)); return r;
}
__device__ __forceinline__ uint32_t tanh2(uint32_t a) {
    uint32_t r; asm("tanh.approx.f16x2 %0, %1;" : "=r"(r) : "r"(a)); return r;
}
__device__ __forceinline__ void red_add_v2(float* p, float a, float b) {
    asm volatile("red.global.add.v2.f32 [%0], {%1,%2};" :: "l"(p), "f"(a), "f"(b) : "memory");
}
__device__ __forceinline__ void red_add_v4(float* p, float a, float b, float c, float d) {
    asm volatile("red.global.add.v4.f32 [%0], {%1,%2,%3,%4};"
                 :: "l"(p), "f"(a), "f"(b), "f"(c), "f"(d) : "memory");
}
__device__ __forceinline__ void mma_f16(float* c, const uint32_t* a, uint32_t b0, uint32_t b1) {
    asm("mma.sync.aligned.m16n8k16.row.col.f32.f16.f16.f32 "
        "{%0,%1,%2,%3}, {%4,%5,%6,%7}, {%8,%9}, {%0,%1,%2,%3};"
        : "+f"(c[0]), "+f"(c[1]), "+f"(c[2]), "+f"(c[3])
        : "r"(a[0]), "r"(a[1]), "r"(a[2]), "r"(a[3]), "r"(b0), "r"(b1));
}
__device__ __forceinline__ int cell1d(float v) {
    int c = (int)floorf((v - ORG) * CINV);
    return min(max(c, 0), GX - 1);
}
__device__ __forceinline__ int permw(int l) {
    return 8*(l >> 3) + 2*(l & 3) + ((l >> 2) & 1);
}

__global__ void prep_kernel(const float* __restrict__ W1,
                            const float* __restrict__ W2,
                            const float* __restrict__ Wout) {
    int h = threadIdx.x;  // 64
    for (int t = h; t < NB*NCELL; t += 64) g_cnt[t] = 0;
    float wv = 0.f;
    #pragma unroll
    for (int c = 0; c < 32; c++) wv = fmaf(W2[h*32 + c], Wout[c], wv);
    #pragma unroll
    for (int d = 0; d < 16; d++) {
        g_UVt[h*32 + d]      = W1[d*64 + h]      * wv;
        g_UVt[h*32 + 16 + d] = W1[(16+d)*64 + h] * wv;
    }
    __syncthreads();
    if (h < 32) {
        float s = 0.f;
        for (int hh = 0; hh < 64; hh++) s += g_UVt[hh*32 + h];
        g_su[h] = s;
        int g = h >> 2, tg = h & 3;
        for (int kt = 0; kt < 4; kt++)
            for (int nt = 0; nt < 4; nt++) {
                int col = nt*8 + g;
                float u0 = g_UVt[(kt*16 + 2*tg    )*32 + col];
                float u1 = g_UVt[(kt*16 + 2*tg + 1)*32 + col];
                float u2 = g_UVt[(kt*16 + 8 + 2*tg    )*32 + col];
                float u3 = g_UVt[(kt*16 + 8 + 2*tg + 1)*32 + col];
                g_UVf2[((kt*4 + nt)*32 + h)*2 + 0] = pkh2(u1, u0);
                g_UVf2[((kt*4 + nt)*32 + h)*2 + 1] = pkh2(u3, u2);
            }
    }
}

__global__ void __launch_bounds__(512) binps_kernel() {
    __shared__ int wsum[16];
    __shared__ int s_cur[NCELL];
    int b = blockIdx.x;
    int c = threadIdx.x;
    int lane = c & 31, wid = c >> 5;
    int v = (c < NCELL) ? g_cnt[b*NCELL + c] : 0;
    int sv = v;
    #pragma unroll
    for (int o = 1; o < 32; o <<= 1) {
        int t = __shfl_up_sync(0xffffffffu, sv, o);
        if (lane >= o) sv += t;
    }
    if (lane == 31) wsum[wid] = sv;
    __syncthreads();
    if (wid == 0) {
        int t = (lane < 16) ? wsum[lane] : 0;
        #pragma unroll
        for (int o = 1; o < 16; o <<= 1) {
            int u = __shfl_up_sync(0xffffffffu, t, o);
            if (lane >= o) t += u;
        }
        if (lane < 16) wsum[lane] = t;
    }
    __syncthreads();
    int incl = sv + (wid > 0 ? wsum[wid - 1] : 0);
    if (c < NCELL) {
        int ex = incl - v;
        g_start[b*(NCELL+1) + c] = ex;
        s_cur[c] = ex;
        g_cnt[b*NCELL + c] = 0;
        if (c == NCELL - 1) g_start[b*(NCELL+1) + NCELL] = incl;
    }
    __syncthreads();
    #pragma unroll
    for (int k = 0; k < NPTS/512; k++) {
        int il = k*512 + c;
        float2 pos = g_pos[b*NPTS + il];
        int cell = cell1d(pos.y) * GX + cell1d(pos.x);
        int slot = atomicAdd(&s_cur[cell], 1);
        g_spt[b*NPTS + slot] = make_float4(pos.x, pos.y, __int_as_float(il), 0.f);
    }
}

__global__ void __launch_bounds__(512) updfeat_kernel(const float* __restrict__ xin,
                                                      const float* __restrict__ W1,
                                                      const float* __restrict__ b1,
                                                      float* __restrict__ out,
                                                      float scale, int use_buf) {
    __shared__ __align__(16) float sW[2048];
    __shared__ float sb[64];
    int tid  = threadIdx.x;
    int lane = tid & 31;
    int wid  = tid >> 5;
    for (int t = tid; t < 2048; t += 512) sW[t] = W1[t];
    if (tid < 64) sb[tid] = b1[tid];
    __syncthreads();

    int pw = permw(lane);
    const float* xs = use_buf ? g_xbuf : xin;
    #pragma unroll
    for (int it = 0; it < 4; it++) {
        int p = blockIdx.x * 64 + wid * 4 + it;
        float xval = 0.f;
        if (lane < 16) {
            float v = xs[p*DD + lane] - scale * g_grad[p*DD + lane];
            xval = v;
            g_xbuf[p*DD + lane] = v;
            out[p*DD + lane]    = v;
            g_grad[p*DD + lane] = 0.f;
        }
        float a0 = sb[2*lane], a1 = sb[2*lane + 1];
        float c0 = 0.f, c1 = 0.f;
        #pragma unroll
        for (int d = 0; d < 16; d++) {
            float xd = __shfl_sync(0xffffffffu, xval, d);
            float2 wa = *reinterpret_cast<const float2*>(&sW[d*64 + 2*lane]);
            float2 wb = *reinterpret_cast<const float2*>(&sW[(16 + d)*64 + 2*lane]);
            a0 = fmaf(xd, wa.x, a0);
            a1 = fmaf(xd, wa.y, a1);
            c0 = fmaf(xd, wb.x, c0);
            c1 = fmaf(xd, wb.y, c1);
        }
        g_Ah[(size_t)p*32 + pw] = pkh2(a1, a0);
        g_Bh[(size_t)p*32 + pw] = pkh2(c1, c0);
        float v0 = __shfl_sync(0xffffffffu, xval, 0);
        float v1 = __shfl_sync(0xffffffffu, xval, 1);
        if (lane == 0) {
            g_pos[p] = make_float2(v0, v1);
            int b = p / NPTS;
            int cell = cell1d(v1) * GX + cell1d(v0);
            atomicAdd(&g_cnt[b*NCELL + cell], 1);
        }
    }
}

__global__ void __launch_bounds__(512) finupd_kernel(float* __restrict__ out) {
    int i = blockIdx.x * 512 + threadIdx.x;
    out[i] = g_xbuf[i] - 0.01f * g_grad[i];
}

__global__ void __launch_bounds__(128, 10) edges_kernel() {
    // all SMEM per-warp; s_key ALIASES s_Bf (keys dead before staging writes)
    __shared__ __align__(16) uint32_t s_Bf[WPB*1024];   // 16 KB
    __shared__ __align__(8)  uint32_t s_Ai2[WPB][32];   // 512 B
    __shared__ int      s_sel[WPB][KSEL];               // 512 B

    const float R2 = 0.08f * 0.08f;
    int tid  = threadIdx.x;
    int lane = tid & 31;
    int w    = tid >> 5;
    int batch = blockIdx.x >> 9;
    int grp   = blockIdx.x & 511;
    int base  = batch * NPTS;

    int il = grp * WPB + w;
    int ig = base + il;
    float2 pi = __ldg(&g_pos[ig]);

    uint32_t* Bfw = s_Bf + w*1024;
    uint64_t* keyw = reinterpret_cast<uint64_t*>(Bfw);   // alias: first 768B of warp's Bf region

    s_Ai2[w][lane] = __ldg(&g_Ah[(size_t)ig*32 + lane]);
    s_sel[w][lane] = il;
    __syncwarp();

    // ---- binned candidate scan ----
    int cx = cell1d(pi.x), cy = cell1d(pi.y);
    int ry0 = max(cy - 1, 0), ry1 = min(cy + 1, GY - 1);
    int rx0 = max(cx - 1, 0), rx1 = min(cx + 1, GX - 1);
    const int* startb = g_start + batch*(NCELL+1);
    int cnt = 0;
    unsigned lt = (1u << lane) - 1u;
    for (int ry = ry0; ry <= ry1; ry++) {
        int s = __ldg(startb + ry*GX + rx0);
        int e = __ldg(startb + ry*GX + rx1 + 1);
        for (int tb = s; tb < e; tb += 32) {
            int t = tb + lane;
            bool in = (t < e);
            float4 pj = in ? __ldg(&g_spt[base + t]) : make_float4(1e9f, 1e9f, 0.f, 0.f);
            int jl = __float_as_int(pj.z);
            float dx = pj.x - pi.x, dy = pj.y - pi.y;
            float d2 = fmaf(dx, dx, dy*dy);
            bool ok = in && (d2 < R2) && (jl != il);
            unsigned m = __ballot_sync(0xffffffffu, ok);
            if (ok) {
                int p = cnt + __popc(m & lt);
                if (p < CAND_MAX)
                    keyw[p] = (((uint64_t)__float_as_uint(d2)) << 32) | (uint32_t)jl;
            }
            cnt += __popc(m);
        }
    }
    int M = min(cnt, CAND_MAX);
    __syncwarp();

    // ---- select K smallest: single-pass multi-rank loop ----
    int S;
    if (M <= KSEL) {
        if (lane < M) s_sel[w][lane] = (int)(uint32_t)keyw[lane];
        S = M;
    } else {
        if (lane == 0 && M < CAND_MAX) keyw[M] = ~0ull;
        __syncwarp();
        uint64_t k0 = keyw[lane];
        uint64_t k1 = (lane + 32 < M) ? keyw[lane + 32] : ~0ull;
        uint64_t k2 = (lane + 64 < M) ? keyw[lane + 64] : ~0ull;
        int r0 = 0, r1 = 0, r2 = 0;
        int Mr = (M + 1) & ~1;
        #pragma unroll 2
        for (int t = 0; t < Mr; t += 2) {
            uint64_t ta = keyw[t];
            uint64_t tb = keyw[t + 1];
            r0 += (int)(ta < k0) + (int)(tb < k0);
            r1 += (int)(ta < k1) + (int)(tb < k1);
            r2 += (int)(ta < k2) + (int)(tb < k2);
        }
        if (r0 < KSEL) s_sel[w][r0] = (int)(uint32_t)k0;
        if (lane + 32 < M && r1 < KSEL) s_sel[w][r1] = (int)(uint32_t)k1;
        if (lane + 64 < M && r2 < KSEL) s_sel[w][r2] = (int)(uint32_t)k2;
        S = KSEL;
    }
    __syncwarp();   // keys fully consumed; Bfw may now be overwritten

    // ---- stage B rows, swizzle: word W of row r -> r*32+((W+4r)&31) ----
    int sel_own = s_sel[w][lane];
    int q = lane & 7;
    #pragma unroll
    for (int i = 0; i < 8; i++) {
        int r  = 4*i + (lane >> 3);
        int jl = __shfl_sync(0xffffffffu, sel_own, r);
        uint4 v = __ldg(reinterpret_cast<const uint4*>(g_Bh + (size_t)(base + jl)*32) + q);
        int word = r*32 + ((4*q + 4*r) & 31);
        *reinterpret_cast<uint4*>(Bfw + word) = v;
    }
    __syncwarp();

    // ---- per-warp GEMM via f16 m16n8k16 ----
    int g2 = lane >> 2, tg = lane & 3;
    bool v0 = (g2      < S), v1 = (g2 + 8  < S);
    bool v2f = (g2 + 16 < S), v3 = (g2 + 24 < S);
    float acci[2][4];
    float accj[2][2][4];
    #pragma unroll
    for (int nt = 0; nt < 2; nt++)
        #pragma unroll
        for (int qq = 0; qq < 4; qq++) acci[nt][qq] = 0.f;
    #pragma unroll
    for (int mt = 0; mt < 2; mt++)
        #pragma unroll
        for (int nt = 0; nt < 2; nt++)
            #pragma unroll
            for (int qq = 0; qq < 4; qq++) accj[mt][nt][qq] = 0.f;

    const uint2* UV = reinterpret_cast<const uint2*>(g_UVf2);
    #pragma unroll
    for (int kt = 0; kt < 4; kt++) {
        uint2 ai = *reinterpret_cast<const uint2*>(&s_Ai2[w][kt*8 + 2*tg]);
        // single swizzle offset for all 4 fragment loads this kt
        int off = (kt*8 + 2*tg + 4*g2) & 31;
        uint32_t A0[2][4];
        #pragma unroll
        for (int mt = 0; mt < 2; mt++) {
            int rA = mt*16 + g2, rB = rA + 8;
            uint2 bA = *reinterpret_cast<const uint2*>(Bfw + rA*32 + off);
            uint2 bB = *reinterpret_cast<const uint2*>(Bfw + rB*32 + off);
            uint32_t t0 = tanh2(hadd2(ai.x, bA.x));
            uint32_t t1 = tanh2(hadd2(ai.x, bB.x));
            uint32_t t2 = tanh2(hadd2(ai.y, bA.y));
            uint32_t t3 = tanh2(hadd2(ai.y, bB.y));
            bool vA = mt ? v2f : v0;
            bool vB = mt ? v3  : v1;
            A0[mt][0] = vA ? hmul2(t0, t0) : 0u;
            A0[mt][1] = vB ? hmul2(t1, t1) : 0u;
            A0[mt][2] = vA ? hmul2(t2, t2) : 0u;
            A0[mt][3] = vB ? hmul2(t3, t3) : 0u;
        }
        #pragma unroll
        for (int nt = 0; nt < 2; nt++) {
            uint2 bb = __ldg(UV + (kt*4 + nt)*32 + lane);
            mma_f16(acci[nt], A0[0], bb.x, bb.y);
            mma_f16(acci[nt], A0[1], bb.x, bb.y);
        }
        #pragma unroll
        for (int nt = 0; nt < 2; nt++) {
            uint2 bb = __ldg(UV + (kt*4 + nt + 2)*32 + lane);
            mma_f16(accj[0][nt], A0[0], bb.x, bb.y);
            mma_f16(accj[1][nt], A0[1], bb.x, bb.y);
        }
    }

    // ---- gj scatter ----
    float2 suv2 = __ldg(reinterpret_cast<const float2*>(g_su + 16 + 2*tg));
    float2 suv3 = __ldg(reinterpret_cast<const float2*>(g_su + 24 + 2*tg));
    float su16 = suv2.x, su17 = suv2.y;
    float su24 = suv3.x, su25 = suv3.y;
    bool evenTg = ((tg & 1) == 0);
    int colbase = (evenTg ? 0 : 8) + 4*(tg >> 1);
    #pragma unroll
    for (int mt = 0; mt < 2; mt++) {
        #pragma unroll
        for (int half = 0; half < 2; half++) {
            int h2 = half*2;
            float a0 = su16 - accj[mt][0][h2];
            float a1 = su17 - accj[mt][0][h2+1];
            float b0 = su24 - accj[mt][1][h2];
            float b1 = su25 - accj[mt][1][h2+1];
            float ra0 = __shfl_xor_sync(0xffffffffu, a0, 1);
            float ra1 = __shfl_xor_sync(0xffffffffu, a1, 1);
            float rb0 = __shfl_xor_sync(0xffffffffu, b0, 1);
            float rb1 = __shfl_xor_sync(0xffffffffu, b1, 1);
            float q0 = evenTg ? a0  : rb0;
            float q1 = evenTg ? a1  : rb1;
            float q2 = evenTg ? ra0 : b0;
            float q3 = evenTg ? ra1 : b1;
            int e = mt*16 + g2 + half*8;
            if (e < S) {
                int jg = base + s_sel[w][e];
                red_add_v4(g_grad + (size_t)jg*16 + colbase, q0, q1, q2, q3);
            }
        }
    }

    // ---- gi: column sums of cols 0..15 ----
    float s00 = acci[0][0] + acci[0][2];
    float s01 = acci[0][1] + acci[0][3];
    float s10 = acci[1][0] + acci[1][2];
    float s11 = acci[1][1] + acci[1][3];
    #pragma unroll
    for (int o = 4; o < 32; o <<= 1) {
        s00 += __shfl_xor_sync(0xffffffffu, s00, o);
        s01 += __shfl_xor_sync(0xffffffffu, s01, o);
        s10 += __shfl_xor_sync(0xffffffffu, s10, o);
        s11 += __shfl_xor_sync(0xffffffffu, s11, o);
    }
    if (g2 == 0) {
        float fs = (float)S;
        float2 su0 = __ldg(reinterpret_cast<const float2*>(g_su + 2*tg));
        float2 su1 = __ldg(reinterpret_cast<const float2*>(g_su + 8 + 2*tg));
        float* gp = g_grad + (size_t)ig*16;
        red_add_v2(gp + 2*tg,     fs*su0.x - s00, fs*su0.y - s01);
        red_add_v2(gp + 8 + 2*tg, fs*su1.x - s10, fs*su1.y - s11);
    }
}

extern "C" void kernel_launch(void* const* d_in, const int* in_sizes, int n_in,
                              void* d_out, int out_size) {
    (void)in_sizes; (void)n_in; (void)out_size;
    const float* x    = (const float*)d_in[0];
    const float* W1   = (const float*)d_in[1];
    const float* b1   = (const float*)d_in[2];
    const float* W2   = (const float*)d_in[3];
    const float* Wout = (const float*)d_in[5];
    float* out = (float*)d_out;

    prep_kernel<<<1, 64>>>(W1, W2, Wout);
    updfeat_kernel<<<BN/64, 512>>>(x, W1, b1, out, 0.0f, 0);
    binps_kernel<<<NB, 512>>>();
    edges_kernel<<<BN/WPB, 128>>>();                            // launch 4: profiled
    updfeat_kernel<<<BN/64, 512>>>(x, W1, b1, out, 0.01f, 1);
    binps_kernel<<<NB, 512>>>();
    edges_kernel<<<BN/WPB, 128>>>();
    finupd_kernel<<<(BN*DD)/512, 512>>>(out);
}